// round 9
// baseline (speedup 1.0000x reference)
#include <cuda_runtime.h>
#include <cuda_fp16.h>
#include <cstdint>

// ---------------------------------------------------------------------------
// Problem constants
// ---------------------------------------------------------------------------
#define BB 512      // batch
#define SS 256      // set size
#define DD 64       // feature dim (K)
#define HH 64       // n_hidden_sets
#define EE 8        // n_elements
#define HE 512      // H*E (N of GEMM)
#define BN_EPS 1e-5f

#define NCTA 304          // 2 per SM on GB300 (152 SMs)
#define K1_THREADS 256
#define UNITS 2048        // 512 b x 4 quarters (64 rows each)

// smem layout (bytes)
#define S_BUF0 0                    // X fp16 unit buf 0 (8 KB)
#define S_BUF1 8192                 // X fp16 unit buf 1 (8 KB)
#define SB     16384                // B fp16 image 64 KB (dead after frag load) | Phase C: US
#define S_TSM  83968                // per-warp T staging: 8 x 64 floats (2 KB)
#define S_WFC  86016                // fc1_w transposed [h][j] 8 KB
#define S_FB   94208                // fc1_b [32]
#define S_CTL  94336                // control ints
#define SM_TOTAL 94400

// ---------------------------------------------------------------------------
// Device scratch (no dynamic allocation allowed)
// ---------------------------------------------------------------------------
__device__ float g_part[BB * 4 * HH];   // per-(b,quarter) partial pooled sums
__device__ int   g_cnt[BB];             // warp-arrival counters (self-resetting)
__device__ float g_u[BB * 32];          // fc1 output
__device__ int   g_done = 0;            // CTA completion counter

__device__ __forceinline__ uint32_t smem_u32(const void* p) {
    uint32_t a;
    asm("{ .reg .u64 t; cvta.to.shared.u64 t, %1; cvt.u32.u64 %0, t; }" : "=r"(a) : "l"(p));
    return a;
}
__device__ __forceinline__ uint32_t swz(uint32_t off) {   // SW128: conflict-free ldmatrix
    return off ^ ((off >> 3) & 0x70);
}
__device__ __forceinline__ float lrelu(float x) { return fmaxf(x, 0.01f * x); }

__device__ __forceinline__ void ldsm_x4(uint32_t addr, uint32_t& r0, uint32_t& r1,
                                        uint32_t& r2, uint32_t& r3) {
    asm volatile("ldmatrix.sync.aligned.m8n8.x4.shared.b16 {%0,%1,%2,%3}, [%4];"
                 : "=r"(r0), "=r"(r1), "=r"(r2), "=r"(r3) : "r"(addr));
}
__device__ __forceinline__ void mma_fp16(float& c0, float& c1, float& c2, float& c3,
                                         uint32_t a0, uint32_t a1, uint32_t a2, uint32_t a3,
                                         uint32_t b0, uint32_t b1) {
    asm volatile("mma.sync.aligned.m16n8k16.row.col.f32.f16.f16.f32 "
                 "{%0,%1,%2,%3}, {%4,%5,%6,%7}, {%8,%9}, {%0,%1,%2,%3};"
                 : "+f"(c0), "+f"(c1), "+f"(c2), "+f"(c3)
                 : "r"(a0), "r"(a1), "r"(a2), "r"(a3), "r"(b0), "r"(b1));
}

// convert 4 float4 (one unit's share) -> swizzled fp16 buffer (f16x2 pack cvt)
__device__ __forceinline__ void cvt_sts_unit(char* smem, int bufoff, int tid,
                                             const float4* v) {
    #pragma unroll
    for (int j = 0; j < 4; j++) {
        int cc = tid + j * 256;            // float4 idx within unit
        int row = cc >> 4, k4 = (cc & 15) << 2;
        __half2 p01 = __floats2half2_rn(v[j].x, v[j].y);
        __half2 p23 = __floats2half2_rn(v[j].z, v[j].w);
        uint32_t sw = swz((uint32_t)row * 128u + (uint32_t)k4 * 2u);
        *(uint2*)(smem + bufoff + sw) =
            make_uint2(*(uint32_t*)&p01, *(uint32_t*)&p23);
    }
}

// ---------------------------------------------------------------------------
// Single persistent kernel: static 64-row unit schedule, warp-level combine
// ---------------------------------------------------------------------------
__global__ __launch_bounds__(K1_THREADS, 2)
void fused_all(const float* __restrict__ X, const float* __restrict__ Wc,
               const float* __restrict__ fc1_w, const float* __restrict__ fc1_b,
               const float* __restrict__ gamma, const float* __restrict__ beta,
               const float* __restrict__ fc2_w, const float* __restrict__ fc2_b,
               float* __restrict__ out) {
    extern __shared__ char smem[];
    const uint32_t sb = smem_u32(smem);
    const int tid  = threadIdx.x;
    const int hb   = tid >> 5;        // warp id == h-block
    const int lane = tid & 31;
    int* ctl = (int*)(smem + S_CTL);  // [0]=last-CTA flag

    // ===== Phase A: build B = Wc^T fp16 SW128 [n][k] image in smem (once) =====
    for (int i = tid; i < 16384; i += K1_THREADS) {
        int kk = i >> 9;               // k = 2*kk
        int n  = i & 511;
        float w0 = Wc[(2 * kk)     * HE + n];
        float w1 = Wc[(2 * kk + 1) * HE + n];
        __half2 h = __floats2half2_rn(w0, w1);
        uint32_t sw = swz((uint32_t)n * 128u + (uint32_t)kk * 4u);
        *(__half2*)(smem + SB + sw) = h;
    }
    for (int i = tid; i < 32 * HH; i += K1_THREADS) {
        int j = i >> 6, h = i & 63;
        ((float*)(smem + S_WFC))[h * 32 + j] = fc1_w[i];
    }
    if (tid < 32) ((float*)(smem + S_FB))[tid] = fc1_b[tid];
    __syncthreads();

    // ===== load all B fragments for this warp's h-block into registers (once)
    uint32_t bf[EE][8];
    #pragma unroll
    for (int e = 0; e < EE; e++) {
        #pragma unroll
        for (int half = 0; half < 2; half++) {
            uint32_t off = (uint32_t)(e * 64 + hb * 8 + (lane & 7)) * 128u
                         + (uint32_t)half * 64u + (uint32_t)(lane >> 3) * 16u;
            uint32_t sw = swz(off);
            ldsm_x4(sb + SB + sw, bf[e][half*4+0], bf[e][half*4+1],
                                   bf[e][half*4+2], bf[e][half*4+3]);
        }
    }

    // ===== Phase B: static unit schedule, software-pipelined =====
    const float4* X4 = (const float4*)X;
    float* tsm_w = (float*)(smem + S_TSM) + hb * HH;   // per-warp T slot

    int u = blockIdx.x;
    // preload first unit's X (b = u>>2, quarter q = u&3)
    {
        const float4* src = X4 + (size_t)(u >> 2) * 4096 + (u & 3) * 1024;
        float4 v[4];
        #pragma unroll
        for (int j = 0; j < 4; j++) v[j] = src[tid + j * 256];
        cvt_sts_unit(smem, S_BUF0, tid, v);
    }
    __syncthreads();
    int cur = 0;

    for (; u < UNITS; u += NCTA) {
        const int b = u >> 2, q = u & 3;
        const int un = u + NCTA;
        const bool have_next = (un < UNITS);

        // ---- issue LDG for next unit (latency hidden behind MMAs)
        float4 v[4];
        if (have_next) {
            const float4* nsrc = X4 + (size_t)(un >> 2) * 4096 + (un & 3) * 1024;
            #pragma unroll
            for (int j = 0; j < 4; j++) v[j] = nsrc[tid + j * 256];
        }

        // ---- MMA over current unit (4 m-tiles of 16 rows)
        float sacc0 = 0.0f, sacc1 = 0.0f;
        const int bufoff = cur ? S_BUF1 : S_BUF0;
        #pragma unroll
        for (int mt = 0; mt < 4; mt++) {
            const int m0 = mt * 16;
            float c[EE][4];
            #pragma unroll
            for (int e = 0; e < EE; e++)
                #pragma unroll
                for (int i = 0; i < 4; i++) c[e][i] = 0.0f;

            #pragma unroll
            for (int ks = 0; ks < 4; ks++) {
                uint32_t off = (uint32_t)(m0 + (lane & 15)) * 128u
                             + (uint32_t)ks * 32u + (uint32_t)(lane >> 4) * 16u;
                uint32_t sw = swz(off);
                uint32_t a0, a1, a2, a3;
                ldsm_x4(sb + bufoff + sw, a0, a1, a2, a3);
                const int i0 = (ks >> 1) * 4 + (ks & 1) * 2;
                #pragma unroll
                for (int e = 0; e < EE; e++)
                    mma_fp16(c[e][0], c[e][1], c[e][2], c[e][3],
                             a0, a1, a2, a3, bf[e][i0], bf[e][i0+1]);
            }

            // max over E first (lrelu monotone -> commutes exactly)
            float v0 = c[0][0], v1 = c[0][1], v2 = c[0][2], v3 = c[0][3];
            #pragma unroll
            for (int e = 1; e < EE; e++) {
                v0 = fmaxf(v0, c[e][0]);
                v1 = fmaxf(v1, c[e][1]);
                v2 = fmaxf(v2, c[e][2]);
                v3 = fmaxf(v3, c[e][3]);
            }
            sacc0 += lrelu(v0) + lrelu(v2);   // col h = hb*8 + (lane%4)*2
            sacc1 += lrelu(v1) + lrelu(v3);   // col h+1
        }

        // ---- warp-level flush: reduce row-owner groups, write partial, count
        #pragma unroll
        for (int o = 4; o <= 16; o <<= 1) {
            sacc0 += __shfl_xor_sync(0xffffffffu, sacc0, o);
            sacc1 += __shfl_xor_sync(0xffffffffu, sacc1, o);
        }
        if (lane < 4)
            *(float2*)&g_part[(size_t)(b * 4 + q) * HH + hb * 8 + lane * 2] =
                make_float2(sacc0, sacc1);
        __syncwarp();
        int old = 0;
        if (lane == 0) {
            __threadfence();
            old = atomicAdd(&g_cnt[b], 1);
        }
        old = __shfl_sync(0xffffffffu, old, 0);

        if (old == 31) {               // last warp for this b: combine + fc1
            __threadfence();           // acquire: other warps' partials visible
            const float* gp = &g_part[(size_t)b * 4 * HH];
            float2 p0 = *(const float2*)&gp[0 * HH + lane * 2];
            float2 p1 = *(const float2*)&gp[1 * HH + lane * 2];
            float2 p2 = *(const float2*)&gp[2 * HH + lane * 2];
            float2 p3 = *(const float2*)&gp[3 * HH + lane * 2];
            // fixed combine order -> deterministic
            tsm_w[lane * 2]     = (p0.x + p1.x) + (p2.x + p3.x);
            tsm_w[lane * 2 + 1] = (p0.y + p1.y) + (p2.y + p3.y);
            __syncwarp();
            const float* wfc = (const float*)(smem + S_WFC);
            float uacc = ((const float*)(smem + S_FB))[lane];
            #pragma unroll 8
            for (int h = 0; h < HH; h++)
                uacc = fmaf(tsm_w[h], wfc[h * 32 + lane], uacc);
            g_u[b * 32 + lane] = uacc;
            if (lane == 0) g_cnt[b] = 0;   // self-reset for graph replay
        }

        // ---- convert + store next unit into the other buffer
        if (have_next) cvt_sts_unit(smem, cur ? S_BUF0 : S_BUF1, tid, v);
        __syncthreads();
        cur ^= 1;
    }

    // ===== Phase C: last CTA runs BatchNorm + LeakyReLU + fc2 inline =====
    __threadfence();
    if (tid == 0) {
        int old = atomicAdd(&g_done, 1);
        ctl[0] = (old == NCTA - 1) ? 1 : 0;
    }
    __syncthreads();
    if (!ctl[0]) return;

    // stage g_u into padded smem US[b][j] stride 33 (B image is dead here)
    float* US = (float*)(smem + SB);
    for (int i = tid; i < BB * 32; i += K1_THREADS)
        US[(i >> 5) * 33 + (i & 31)] = g_u[i];
    float* PS   = (float*)(smem + S_BUF0);       // [8][32] partials
    float* MEAN = PS + 256;                      // [32]
    float* RS   = MEAN + 32;                     // [32]
    __syncthreads();

    const int j = tid & 31, g = tid >> 5;        // 8 groups x 32 features
    {
        float s = 0.0f;
        #pragma unroll 8
        for (int bb = g * 64; bb < g * 64 + 64; bb++) s += US[bb * 33 + j];
        PS[g * 32 + j] = s;
    }
    __syncthreads();
    if (tid < 32) {
        float m = 0.0f;
        #pragma unroll
        for (int g2 = 0; g2 < 8; g2++) m += PS[g2 * 32 + tid];
        MEAN[tid] = m * (1.0f / (float)BB);
    }
    __syncthreads();
    {
        float mu = MEAN[j], s = 0.0f;
        #pragma unroll 8
        for (int bb = g * 64; bb < g * 64 + 64; bb++) {
            float d = US[bb * 33 + j] - mu;
            s += d * d;
        }
        PS[g * 32 + j] = s;
    }
    __syncthreads();
    if (tid < 32) {
        float v = 0.0f;
        #pragma unroll
        for (int g2 = 0; g2 < 8; g2++) v += PS[g2 * 32 + tid];
        RS[tid] = rsqrtf(v * (1.0f / (float)BB) + BN_EPS);
    }
    __syncthreads();

    for (int bb = tid; bb < BB; bb += K1_THREADS) {
        float a = __ldg(&fc2_b[0]);
        #pragma unroll
        for (int j2 = 0; j2 < 32; j2++) {
            float y = (US[bb * 33 + j2] - MEAN[j2]) * RS[j2] * __ldg(&gamma[j2]) + __ldg(&beta[j2]);
            a = fmaf(lrelu(y), __ldg(&fc2_w[j2]), a);
        }
        out[bb] = a;
    }

    // reset counter for next graph replay
    if (tid == 0) g_done = 0;
}

// ---------------------------------------------------------------------------
extern "C" void kernel_launch(void* const* d_in, const int* in_sizes, int n_in,
                              void* d_out, int out_size) {
    const float* X     = (const float*)d_in[0];
    const float* Wc    = (const float*)d_in[1];
    const float* fc1_w = (const float*)d_in[2];
    const float* fc1_b = (const float*)d_in[3];
    const float* gamma = (const float*)d_in[4];
    const float* beta  = (const float*)d_in[5];
    const float* fc2_w = (const float*)d_in[6];
    const float* fc2_b = (const float*)d_in[7];
    float* out = (float*)d_out;

    cudaFuncSetAttribute(fused_all, cudaFuncAttributeMaxDynamicSharedMemorySize, SM_TOTAL);
    fused_all<<<NCTA, K1_THREADS, SM_TOTAL>>>(X, Wc, fc1_w, fc1_b,
                                              gamma, beta, fc2_w, fc2_b, out);
}

// round 10
// speedup vs baseline: 1.0841x; 1.0841x over previous
#include <cuda_runtime.h>
#include <cuda_fp16.h>
#include <cstdint>

// ---------------------------------------------------------------------------
// Problem constants
// ---------------------------------------------------------------------------
#define BB 512      // batch
#define SS 256      // set size
#define DD 64       // feature dim (K)
#define HH 64       // n_hidden_sets
#define EE 8        // n_elements
#define HE 512      // H*E (N of GEMM)
#define BN_EPS 1e-5f

#define NCTA 304          // 2 per SM on GB300 (152 SMs)
#define K1_THREADS 256
#define UNITS 2048        // 512 b x 4 quarters (64 rows each)

// smem layout (bytes)
#define S_BUF0 0                    // X fp16 unit buf 0 (8 KB)
#define S_BUF1 8192                 // X fp16 unit buf 1 (8 KB)
#define SB     16384                // B fp16 image 64 KB (dead after frag load) | Phase C: US
#define S_TSM  83968                // warp-0 T staging: 64 floats
#define S_WFC  84224                // fc1_w transposed [h][j] 8 KB
#define S_FB   92416                // fc1_b [32]
#define S_CTL  92544                // control ints
#define SM_TOTAL 92608

// ---------------------------------------------------------------------------
// Device scratch (no dynamic allocation allowed)
// ---------------------------------------------------------------------------
__device__ float g_part[BB * 4 * HH];   // per-(b,quarter) partial pooled sums
__device__ int   g_cnt[BB];             // quarter-arrival counters (self-resetting)
__device__ float g_u[BB * 32];          // fc1 output
__device__ int   g_done = 0;            // CTA completion counter

__device__ __forceinline__ uint32_t smem_u32(const void* p) {
    uint32_t a;
    asm("{ .reg .u64 t; cvta.to.shared.u64 t, %1; cvt.u32.u64 %0, t; }" : "=r"(a) : "l"(p));
    return a;
}
__device__ __forceinline__ uint32_t swz(uint32_t off) {   // SW128: conflict-free ldmatrix
    return off ^ ((off >> 3) & 0x70);
}
__device__ __forceinline__ float lrelu(float x) { return fmaxf(x, 0.01f * x); }

__device__ __forceinline__ void ldsm_x4(uint32_t addr, uint32_t& r0, uint32_t& r1,
                                        uint32_t& r2, uint32_t& r3) {
    asm volatile("ldmatrix.sync.aligned.m8n8.x4.shared.b16 {%0,%1,%2,%3}, [%4];"
                 : "=r"(r0), "=r"(r1), "=r"(r2), "=r"(r3) : "r"(addr));
}
__device__ __forceinline__ void mma_fp16(float& c0, float& c1, float& c2, float& c3,
                                         uint32_t a0, uint32_t a1, uint32_t a2, uint32_t a3,
                                         uint32_t b0, uint32_t b1) {
    asm volatile("mma.sync.aligned.m16n8k16.row.col.f32.f16.f16.f32 "
                 "{%0,%1,%2,%3}, {%4,%5,%6,%7}, {%8,%9}, {%0,%1,%2,%3};"
                 : "+f"(c0), "+f"(c1), "+f"(c2), "+f"(c3)
                 : "r"(a0), "r"(a1), "r"(a2), "r"(a3), "r"(b0), "r"(b1));
}

// convert 4 float4 (one unit's share) -> swizzled fp16 buffer (f16x2 pack cvt)
__device__ __forceinline__ void cvt_sts_unit(char* smem, int bufoff, int tid,
                                             const float4* v) {
    #pragma unroll
    for (int j = 0; j < 4; j++) {
        int cc = tid + j * 256;            // float4 idx within unit
        int row = cc >> 4, k4 = (cc & 15) << 2;
        __half2 p01 = __floats2half2_rn(v[j].x, v[j].y);
        __half2 p23 = __floats2half2_rn(v[j].z, v[j].w);
        uint32_t sw = swz((uint32_t)row * 128u + (uint32_t)k4 * 2u);
        *(uint2*)(smem + bufoff + sw) =
            make_uint2(*(uint32_t*)&p01, *(uint32_t*)&p23);
    }
}

// ---------------------------------------------------------------------------
// Single persistent kernel: static 64-row unit schedule, CTA-level combine
// ---------------------------------------------------------------------------
__global__ __launch_bounds__(K1_THREADS, 2)
void fused_all(const float* __restrict__ X, const float* __restrict__ Wc,
               const float* __restrict__ fc1_w, const float* __restrict__ fc1_b,
               const float* __restrict__ gamma, const float* __restrict__ beta,
               const float* __restrict__ fc2_w, const float* __restrict__ fc2_b,
               float* __restrict__ out) {
    extern __shared__ char smem[];
    const uint32_t sb = smem_u32(smem);
    const int tid  = threadIdx.x;
    const int hb   = tid >> 5;        // warp id == h-block
    const int lane = tid & 31;
    int* ctl = (int*)(smem + S_CTL);  // [0]=last-CTA flag

    // ===== Phase A: build B = Wc^T fp16 SW128 [n][k] image in smem (once) =====
    for (int i = tid; i < 16384; i += K1_THREADS) {
        int kk = i >> 9;               // k = 2*kk
        int n  = i & 511;
        float w0 = Wc[(2 * kk)     * HE + n];
        float w1 = Wc[(2 * kk + 1) * HE + n];
        __half2 h = __floats2half2_rn(w0, w1);
        uint32_t sw = swz((uint32_t)n * 128u + (uint32_t)kk * 4u);
        *(__half2*)(smem + SB + sw) = h;
    }
    for (int i = tid; i < 32 * HH; i += K1_THREADS) {
        int j = i >> 6, h = i & 63;
        ((float*)(smem + S_WFC))[h * 32 + j] = fc1_w[i];
    }
    if (tid < 32) ((float*)(smem + S_FB))[tid] = fc1_b[tid];
    __syncthreads();

    // ===== load all B fragments for this warp's h-block into registers (once)
    uint32_t bf[EE][8];
    #pragma unroll
    for (int e = 0; e < EE; e++) {
        #pragma unroll
        for (int half = 0; half < 2; half++) {
            uint32_t off = (uint32_t)(e * 64 + hb * 8 + (lane & 7)) * 128u
                         + (uint32_t)half * 64u + (uint32_t)(lane >> 3) * 16u;
            uint32_t sw = swz(off);
            ldsm_x4(sb + SB + sw, bf[e][half*4+0], bf[e][half*4+1],
                                   bf[e][half*4+2], bf[e][half*4+3]);
        }
    }

    // ===== Phase B: static unit schedule, software-pipelined =====
    const float4* X4 = (const float4*)X;
    float* tsm0 = (float*)(smem + S_TSM);        // warp-0 combine staging

    int u = blockIdx.x;
    // preload first unit's X (b = u>>2, quarter q = u&3)
    {
        const float4* src = X4 + (size_t)(u >> 2) * 4096 + (u & 3) * 1024;
        float4 v[4];
        #pragma unroll
        for (int j = 0; j < 4; j++) v[j] = src[tid + j * 256];
        cvt_sts_unit(smem, S_BUF0, tid, v);
    }
    __syncthreads();
    int cur = 0;

    for (; u < UNITS; u += NCTA) {
        const int b = u >> 2, q = u & 3;
        const int un = u + NCTA;
        const bool have_next = (un < UNITS);

        // ---- issue LDG for next unit (latency hidden behind MMAs)
        float4 v[4];
        if (have_next) {
            const float4* nsrc = X4 + (size_t)(un >> 2) * 4096 + (un & 3) * 1024;
            #pragma unroll
            for (int j = 0; j < 4; j++) v[j] = nsrc[tid + j * 256];
        }

        // ---- MMA over current unit (4 m-tiles of 16 rows)
        float sacc0 = 0.0f, sacc1 = 0.0f;
        const int bufoff = cur ? S_BUF1 : S_BUF0;
        #pragma unroll
        for (int mt = 0; mt < 4; mt++) {
            const int m0 = mt * 16;
            float c[EE][4];
            #pragma unroll
            for (int e = 0; e < EE; e++)
                #pragma unroll
                for (int i = 0; i < 4; i++) c[e][i] = 0.0f;

            #pragma unroll
            for (int ks = 0; ks < 4; ks++) {
                uint32_t off = (uint32_t)(m0 + (lane & 15)) * 128u
                             + (uint32_t)ks * 32u + (uint32_t)(lane >> 4) * 16u;
                uint32_t sw = swz(off);
                uint32_t a0, a1, a2, a3;
                ldsm_x4(sb + bufoff + sw, a0, a1, a2, a3);
                const int i0 = (ks >> 1) * 4 + (ks & 1) * 2;
                #pragma unroll
                for (int e = 0; e < EE; e++)
                    mma_fp16(c[e][0], c[e][1], c[e][2], c[e][3],
                             a0, a1, a2, a3, bf[e][i0], bf[e][i0+1]);
            }

            // max over E first (lrelu monotone -> commutes exactly)
            float v0 = c[0][0], v1 = c[0][1], v2 = c[0][2], v3 = c[0][3];
            #pragma unroll
            for (int e = 1; e < EE; e++) {
                v0 = fmaxf(v0, c[e][0]);
                v1 = fmaxf(v1, c[e][1]);
                v2 = fmaxf(v2, c[e][2]);
                v3 = fmaxf(v3, c[e][3]);
            }
            sacc0 += lrelu(v0) + lrelu(v2);   // col h = hb*8 + (lane%4)*2
            sacc1 += lrelu(v1) + lrelu(v3);   // col h+1
        }

        // ---- flush quarter partial (release: STG then warp-wide fence)
        #pragma unroll
        for (int o = 4; o <= 16; o <<= 1) {
            sacc0 += __shfl_xor_sync(0xffffffffu, sacc0, o);
            sacc1 += __shfl_xor_sync(0xffffffffu, sacc1, o);
        }
        if (lane < 4)
            *(float2*)&g_part[(size_t)(b * 4 + q) * HH + hb * 8 + lane * 2] =
                make_float2(sacc0, sacc1);
        __threadfence();

        // ---- convert + store next unit into the other buffer
        if (have_next) cvt_sts_unit(smem, cur ? S_BUF0 : S_BUF1, tid, v);
        __syncthreads();   // orders all warps' fenced STGs before the count; swaps bufs
        cur ^= 1;

        // ---- CTA-level arrival count; 4th CTA's warp 0 combines + fc1
        //      (only warp 0 stalls on the atomic; others proceed to next MMAs)
        if (hb == 0) {
            int old = 0;
            if (lane == 0) old = atomicAdd(&g_cnt[b], 1);
            old = __shfl_sync(0xffffffffu, old, 0);
            if (old == 3) {
                __threadfence();   // acquire: other CTAs' partials visible
                const float* gp = &g_part[(size_t)b * 4 * HH];
                float2 p0 = *(const float2*)&gp[0 * HH + lane * 2];
                float2 p1 = *(const float2*)&gp[1 * HH + lane * 2];
                float2 p2 = *(const float2*)&gp[2 * HH + lane * 2];
                float2 p3 = *(const float2*)&gp[3 * HH + lane * 2];
                // fixed combine order -> deterministic
                tsm0[lane * 2]     = (p0.x + p1.x) + (p2.x + p3.x);
                tsm0[lane * 2 + 1] = (p0.y + p1.y) + (p2.y + p3.y);
                __syncwarp();
                const float* wfc = (const float*)(smem + S_WFC);
                float uacc = ((const float*)(smem + S_FB))[lane];
                #pragma unroll 8
                for (int h = 0; h < HH; h++)
                    uacc = fmaf(tsm0[h], wfc[h * 32 + lane], uacc);
                g_u[b * 32 + lane] = uacc;
                if (lane == 0) g_cnt[b] = 0;   // self-reset for graph replay
            }
        }
    }

    // ===== Phase C: last CTA runs BatchNorm + LeakyReLU + fc2 inline =====
    __threadfence();
    if (tid == 0) {
        int old = atomicAdd(&g_done, 1);
        ctl[0] = (old == NCTA - 1) ? 1 : 0;
    }
    __syncthreads();
    if (!ctl[0]) return;

    // stage g_u into padded smem US[b][j] stride 33 (B image is dead here)
    float* US = (float*)(smem + SB);
    for (int i = tid; i < BB * 32; i += K1_THREADS)
        US[(i >> 5) * 33 + (i & 31)] = g_u[i];
    float* PS   = (float*)(smem + S_BUF0);       // [8][32] partials
    float* MEAN = PS + 256;                      // [32]
    float* RS   = MEAN + 32;                     // [32]
    __syncthreads();

    const int j = tid & 31, g = tid >> 5;        // 8 groups x 32 features
    {
        float s = 0.0f;
        #pragma unroll 8
        for (int bb = g * 64; bb < g * 64 + 64; bb++) s += US[bb * 33 + j];
        PS[g * 32 + j] = s;
    }
    __syncthreads();
    if (tid < 32) {
        float m = 0.0f;
        #pragma unroll
        for (int g2 = 0; g2 < 8; g2++) m += PS[g2 * 32 + tid];
        MEAN[tid] = m * (1.0f / (float)BB);
    }
    __syncthreads();
    {
        float mu = MEAN[j], s = 0.0f;
        #pragma unroll 8
        for (int bb = g * 64; bb < g * 64 + 64; bb++) {
            float d = US[bb * 33 + j] - mu;
            s += d * d;
        }
        PS[g * 32 + j] = s;
    }
    __syncthreads();
    if (tid < 32) {
        float v = 0.0f;
        #pragma unroll
        for (int g2 = 0; g2 < 8; g2++) v += PS[g2 * 32 + tid];
        RS[tid] = rsqrtf(v * (1.0f / (float)BB) + BN_EPS);
    }
    __syncthreads();

    for (int bb = tid; bb < BB; bb += K1_THREADS) {
        float a = __ldg(&fc2_b[0]);
        #pragma unroll
        for (int j2 = 0; j2 < 32; j2++) {
            float y = (US[bb * 33 + j2] - MEAN[j2]) * RS[j2] * __ldg(&gamma[j2]) + __ldg(&beta[j2]);
            a = fmaf(lrelu(y), __ldg(&fc2_w[j2]), a);
        }
        out[bb] = a;
    }

    // reset counter for next graph replay
    if (tid == 0) g_done = 0;
}

// ---------------------------------------------------------------------------
extern "C" void kernel_launch(void* const* d_in, const int* in_sizes, int n_in,
                              void* d_out, int out_size) {
    const float* X     = (const float*)d_in[0];
    const float* Wc    = (const float*)d_in[1];
    const float* fc1_w = (const float*)d_in[2];
    const float* fc1_b = (const float*)d_in[3];
    const float* gamma = (const float*)d_in[4];
    const float* beta  = (const float*)d_in[5];
    const float* fc2_w = (const float*)d_in[6];
    const float* fc2_b = (const float*)d_in[7];
    float* out = (float*)d_out;

    cudaFuncSetAttribute(fused_all, cudaFuncAttributeMaxDynamicSharedMemorySize, SM_TOTAL);
    fused_all<<<NCTA, K1_THREADS, SM_TOTAL>>>(X, Wc, fc1_w, fc1_b,
                                              gamma, beta, fc2_w, fc2_b, out);
}